// round 15
// baseline (speedup 1.0000x reference)
#include <cuda_runtime.h>
#include <cuda_fp16.h>
#include <cstdint>

// Problem constants
#define BB 2
#define SSQ 2048
#define DDIM 2048
#define HH 16
#define M1 (BB * SSQ)      // 4096
#define N1 (3 * DDIM)      // 6144
#define FB (BB * HH)       // 32 (b,h) pairs

// ---------------------------------------------------------------------------
// Scratch (__device__ globals). fp16 operands, all 1-digit.
// ---------------------------------------------------------------------------
__device__ __half g_xh [(size_t)M1 * DDIM];
__device__ __half g_w1h[(size_t)N1 * DDIM];
__device__ __half g_w2h[(size_t)DDIM * DDIM];
__device__ __half g_ah [(size_t)M1 * DDIM];           // flash out (GEMM2 A)
// flash operands, layout [bh][s][128]
__device__ __half g_qh[(size_t)FB * SSQ * 128];
__device__ __half g_kh[(size_t)FB * SSQ * 128];
__device__ __half g_vh[(size_t)FB * SSQ * 128];

__device__ __forceinline__ uint32_t smem_u32(const void* p) {
    uint32_t a;
    asm("{ .reg .u64 t; cvta.to.shared.u64 t, %1; cvt.u32.u64 %0, t; }"
        : "=r"(a) : "l"(p));
    return a;
}

#define LDMX4(R, A) \
    asm volatile("ldmatrix.sync.aligned.m8n8.x4.shared.b16 {%0,%1,%2,%3}, [%4];" \
        : "=r"((R)[0]), "=r"((R)[1]), "=r"((R)[2]), "=r"((R)[3]) : "r"(A))
#define LDMX4T(R, A) \
    asm volatile("ldmatrix.sync.aligned.m8n8.x4.trans.shared.b16 {%0,%1,%2,%3}, [%4];" \
        : "=r"((R)[0]), "=r"((R)[1]), "=r"((R)[2]), "=r"((R)[3]) : "r"(A))

// fp32-accumulate HMMA (flash)
#define MMA_F16(ac, a, b0v, b1v) \
    asm volatile("mma.sync.aligned.m16n8k16.row.col.f32.f16.f16.f32 " \
        "{%0,%1,%2,%3},{%4,%5,%6,%7},{%8,%9},{%0,%1,%2,%3};" \
        : "+f"((ac)[0]), "+f"((ac)[1]), "+f"((ac)[2]), "+f"((ac)[3]) \
        : "r"((a)[0]), "r"((a)[1]), "r"((a)[2]), "r"((a)[3]), \
          "r"(b0v), "r"(b1v))

// fp16-accumulate HMMA (GEMM chunk accumulation)
#define MMA_F16ACC(d, a, b0v, b1v) \
    asm volatile("mma.sync.aligned.m16n8k16.row.col.f16.f16.f16.f16 " \
        "{%0,%1},{%2,%3,%4,%5},{%6,%7},{%0,%1};" \
        : "+r"((d)[0]), "+r"((d)[1]) \
        : "r"((a)[0]), "r"((a)[1]), "r"((a)[2]), "r"((a)[3]), \
          "r"(b0v), "r"(b1v))

#define CP_ASYNC16(s, g) \
    asm volatile("cp.async.cg.shared.global [%0], [%1], 16;" :: "r"(s), "l"(g))
#define CP_COMMIT() asm volatile("cp.async.commit_group;" ::: "memory")
#define CP_WAIT1()  asm volatile("cp.async.wait_group 1;" ::: "memory")
#define CP_WAIT0()  asm volatile("cp.async.wait_group 0;" ::: "memory")

__device__ __forceinline__ uint32_t pack_h2(float x, float y) {
    __half2 h = __floats2half2_rn(x, y);
    return *reinterpret_cast<uint32_t*>(&h);
}

// ---------------------------------------------------------------------------
// fp32 -> fp16 convert
// ---------------------------------------------------------------------------
__global__ __launch_bounds__(256) void cvt_h(
    const float* __restrict__ src, __half* __restrict__ dst, int n4)
{
    int i = blockIdx.x * blockDim.x + threadIdx.x;
    if (i >= n4) return;
    float4 v = ((const float4*)src)[i];
    ((uint32_t*)dst)[i * 2 + 0] = pack_h2(v.x, v.y);
    ((uint32_t*)dst)[i * 2 + 1] = pack_h2(v.z, v.w);
}

// ---------------------------------------------------------------------------
// mma.sync fp16 GEMM with CHUNK-LOCAL f16 accumulation:
// within each k=32 chunk, 2 HMMAs chain in f16; the chunk result is
// promoted and added to fp32 accumulators (error ~2.4e-4 per GEMM).
// CTA 128x128, 512 threads (16 warps 4x4, warp tile 32x32), k-chunk 32,
// double-buffered cp.async.
//  MODE 0: plain fp32 store;  MODE 1: fused RoPE + relayout (q/k/v)
// ---------------------------------------------------------------------------
#define KC 32
#define AST 40                           // padded row stride (fp16, 80 B)
#define TILE_B 10240                     // one 128x32 tile (bytes)
#define STAGE (2 * TILE_B)               // A, B
#define GEMM_SMEM (2 * STAGE)            // 40960

template <int MODE>
__global__ __launch_bounds__(512, 1) void mma_gemm_t(
    const __half* __restrict__ A, const __half* __restrict__ B,
    float* __restrict__ C, int Ntot, int K,
    const float* __restrict__ fc, const float* __restrict__ fs)
{
    extern __shared__ __half smh[];
    const uint32_t sbase = smem_u32(smh);
    const int t = threadIdx.x;
    const int lane = t & 31, warp = t >> 5;
    const int bm = blockIdx.y << 7;
    const int bn = blockIdx.x << 7;
    const int wm = (warp >> 2) << 5;   // 0,32,64,96
    const int wn = (warp & 3) << 5;    // 0,32,64,96

    // loader mapping: row t>>2 (0..127), 16B-chunk t&3 (of 4 per 64B row)
    const int rL = t >> 2;
    const int cL = t & 3;
    const __half* gA = A + (size_t)(bm + rL) * K + cL * 8;
    const __half* gB = B + (size_t)(bn + rL) * K + cL * 8;
    const uint32_t sA = sbase + rL * (AST * 2) + cL * 16;
    const uint32_t sB = sA + TILE_B;

    auto load_stage = [&](int kc, int buf) {
        const uint32_t so = buf * STAGE;
        const int go = kc * KC;
        CP_ASYNC16(sA + so, gA + go);
        CP_ASYNC16(sB + so, gB + go);
        CP_COMMIT();
    };

    float acc[2][4][4] = {};
    const int NIT = K / KC;

    load_stage(0, 0);

    const int ldrow = lane & 15;
    const int ldcol = (lane >> 4) << 3;

    for (int it = 0; it < NIT; it++) {
        if (it + 1 < NIT) { load_stage(it + 1, (it + 1) & 1); CP_WAIT1(); }
        else              { CP_WAIT0(); }
        __syncthreads();

        const uint32_t sb = sbase + (it & 1) * STAGE;
        uint32_t hacc[2][4][2] = {};           // chunk-local f16 accumulators
#pragma unroll
        for (int kh = 0; kh < 2; kh++) {
            uint32_t aF[2][4], bF[4][2];
            const int colb = (kh * 16 + ldcol) * 2;
#pragma unroll
            for (int mt = 0; mt < 2; mt++) {
                uint32_t ra = sb + (wm + mt * 16 + ldrow) * (AST * 2) + colb;
                LDMX4(aF[mt], ra);
            }
#pragma unroll
            for (int n2 = 0; n2 < 2; n2++) {
                uint32_t rb = sb + TILE_B +
                              (wn + n2 * 16 + ldrow) * (AST * 2) + colb;
                uint32_t r[4];
                LDMX4(r, rb);
                bF[n2 * 2 + 0][0] = r[0]; bF[n2 * 2 + 0][1] = r[2];
                bF[n2 * 2 + 1][0] = r[1]; bF[n2 * 2 + 1][1] = r[3];
            }
#pragma unroll
            for (int mt = 0; mt < 2; mt++) {
#pragma unroll
                for (int nt = 0; nt < 4; nt++)
                    MMA_F16ACC(hacc[mt][nt], aF[mt], bF[nt][0], bF[nt][1]);
            }
        }
        // promote chunk result to fp32
#pragma unroll
        for (int mt = 0; mt < 2; mt++) {
#pragma unroll
            for (int nt = 0; nt < 4; nt++) {
                float2 f0 = __half22float2(
                    *reinterpret_cast<__half2*>(&hacc[mt][nt][0]));
                float2 f1 = __half22float2(
                    *reinterpret_cast<__half2*>(&hacc[mt][nt][1]));
                acc[mt][nt][0] += f0.x; acc[mt][nt][1] += f0.y;
                acc[mt][nt][2] += f1.x; acc[mt][nt][3] += f1.y;
            }
        }
        __syncthreads();
    }

    const int grp = lane >> 2, qq = (lane & 3) << 1;

    if (MODE == 0) {
#pragma unroll
        for (int mt = 0; mt < 2; mt++) {
#pragma unroll
            for (int nt = 0; nt < 4; nt++) {
                float* p = C + (size_t)(bm + wm + mt * 16 + grp) * Ntot
                             + bn + wn + nt * 8 + qq;
                *(float2*)p = make_float2(acc[mt][nt][0], acc[mt][nt][1]);
                *(float2*)(p + (size_t)8 * Ntot) =
                    make_float2(acc[mt][nt][2], acc[mt][nt][3]);
            }
        }
    } else {
        // fused RoPE + relayout; CTA-uniform region (q/k/v)
        const int region = bn >> 11;            // 0=q, 1=k, 2=v
        const float scale = 0.08838834764831845f; // 1/sqrt(128)
#pragma unroll
        for (int mt = 0; mt < 2; mt++) {
            const int r0 = bm + wm + mt * 16 + grp;
            const int b  = r0 >> 11;
            const int s0 = r0 & (SSQ - 1);
            const int s1 = s0 + 8;
#pragma unroll
            for (int nt = 0; nt < 4; nt++) {
                const int c  = bn + wn + nt * 8 + qq;
                const int cr = c & (DDIM - 1);
                const int h  = cr >> 7;
                const int ch = cr & 127;
                const int i  = ch >> 1;
                const size_t ob = ((size_t)(b * HH + h) * SSQ);
                const size_t o0 = (ob + s0) * 128 + ch;
                const size_t o1 = (ob + s1) * 128 + ch;
                float x0 = acc[mt][nt][0], y0 = acc[mt][nt][1];
                float x1 = acc[mt][nt][2], y1 = acc[mt][nt][3];
                if (region == 2) {
                    *(uint32_t*)(g_vh + o0) = pack_h2(x0, y0);
                    *(uint32_t*)(g_vh + o1) = pack_h2(x1, y1);
                } else {
                    float c0 = fc[(s0 << 6) + i], sn0 = fs[(s0 << 6) + i];
                    float c1 = fc[(s1 << 6) + i], sn1 = fs[(s1 << 6) + i];
                    float rx0 = x0 * c0 - y0 * sn0, ry0 = x0 * sn0 + y0 * c0;
                    float rx1 = x1 * c1 - y1 * sn1, ry1 = x1 * sn1 + y1 * c1;
                    if (region == 0) {
                        *(uint32_t*)(g_qh + o0) = pack_h2(rx0 * scale, ry0 * scale);
                        *(uint32_t*)(g_qh + o1) = pack_h2(rx1 * scale, ry1 * scale);
                    } else {
                        *(uint32_t*)(g_kh + o0) = pack_h2(rx0, ry0);
                        *(uint32_t*)(g_kh + o1) = pack_h2(rx1, ry1);
                    }
                }
            }
        }
    }
}

// ---------------------------------------------------------------------------
// Flash attention on fp16 mma.sync (fp32 accumulate) — unchanged.
// ---------------------------------------------------------------------------
#define FSTR 136
#define FTILE (64 * FSTR)
#define QTILE (128 * FSTR)
#define FLASH_SMEM ((QTILE + 4 * FTILE) * 2)   // 104448 bytes

__global__ __launch_bounds__(256, 1) void flash_mma(
    const __half* __restrict__ qh_, const __half* __restrict__ kh_,
    const __half* __restrict__ vh_, __half* __restrict__ oh)
{
    extern __shared__ __half fsm[];
    const uint32_t sb = smem_u32(fsm);
    const int t = threadIdx.x;
    const int lane = t & 31, warp = t >> 5;
    const int qt = (int)gridDim.x - 1 - (int)blockIdx.x;
    const int bh = blockIdx.y;
    const int q0 = qt << 7;
    const size_t bhbase = (size_t)bh * SSQ * 128;

    const int ldr = lane & 15;
    const int ldc = (lane >> 4) << 3;
    const int grp = lane >> 2;
    const int qq  = (lane & 3) << 1;

    // stage Q
    {
        int r = t >> 1;
        int e0 = (t & 1) << 6;
        const __half* src = qh_ + bhbase + (size_t)(q0 + r) * 128 + e0;
        uint32_t s0 = sb + (r * FSTR + e0) * 2;
#pragma unroll
        for (int c = 0; c < 8; c++)
            CP_ASYNC16(s0 + c * 16, src + c * 8);
        CP_COMMIT();
    }

    auto load_kv = [&](int kt, int buf) {
        int r = t >> 2;
        int e0 = (t & 3) << 5;
        size_t g0 = bhbase + (size_t)(kt * 64 + r) * 128 + e0;
        const __half* srcs[2] = { kh_ + g0, vh_ + g0 };
        uint32_t s0 = sb + (QTILE + buf * 2 * FTILE + r * FSTR + e0) * 2;
#pragma unroll
        for (int tile = 0; tile < 2; tile++)
#pragma unroll
            for (int c = 0; c < 4; c++)
                CP_ASYNC16(s0 + tile * FTILE * 2 + c * 16, srcs[tile] + c * 8);
        CP_COMMIT();
    };

    CP_WAIT0();
    __syncthreads();
    uint32_t qf[8][4];
    const int wrow = warp << 4;
#pragma unroll
    for (int d = 0; d < 8; d++) {
        uint32_t a = sb + ((wrow + ldr) * FSTR + d * 16 + ldc) * 2;
        LDMX4(qf[d], a);
    }

    const int ktmax = 2 * qt + 1;
    load_kv(0, 0);
    load_kv(1, 1);

    float Of[16][4] = {};
    float m0 = -1e30f, m1 = -1e30f, l0 = 0.f, l1 = 0.f;

    for (int kt = 0; kt <= ktmax; kt++) {
        if (kt == ktmax) { CP_WAIT0(); } else { CP_WAIT1(); }
        __syncthreads();

        const uint32_t kvb = sb + (QTILE + (kt & 1) * 2 * FTILE) * 2;

        float Sf[8][4] = {};
#pragma unroll
        for (int d = 0; d < 8; d++) {
#pragma unroll
            for (int n4 = 0; n4 < 4; n4++) {
                uint32_t addr = kvb + ((n4 * 16 + ldr) * FSTR + d * 16 + ldc) * 2;
                uint32_t kb[4];
                LDMX4(kb, addr);
                MMA_F16(Sf[2 * n4],     qf[d], kb[0], kb[2]);
                MMA_F16(Sf[2 * n4 + 1], qf[d], kb[1], kb[3]);
            }
        }

        const int r0 = q0 + wrow + grp;
        if (kt >= 2 * qt) {
#pragma unroll
            for (int nb = 0; nb < 8; nb++) {
#pragma unroll
                for (int j = 0; j < 2; j++) {
                    int key = kt * 64 + nb * 8 + qq + j;
                    if (key > r0)     Sf[nb][j]     = -1e30f;
                    if (key > r0 + 8) Sf[nb][2 + j] = -1e30f;
                }
            }
        }

        float mx0 = -1e30f, mx1 = -1e30f;
#pragma unroll
        for (int nb = 0; nb < 8; nb++) {
            mx0 = fmaxf(mx0, fmaxf(Sf[nb][0], Sf[nb][1]));
            mx1 = fmaxf(mx1, fmaxf(Sf[nb][2], Sf[nb][3]));
        }
        mx0 = fmaxf(mx0, __shfl_xor_sync(0xffffffff, mx0, 1));
        mx0 = fmaxf(mx0, __shfl_xor_sync(0xffffffff, mx0, 2));
        mx1 = fmaxf(mx1, __shfl_xor_sync(0xffffffff, mx1, 1));
        mx1 = fmaxf(mx1, __shfl_xor_sync(0xffffffff, mx1, 2));
        float mn0 = fmaxf(m0, mx0), mn1 = fmaxf(m1, mx1);
        float a0 = __expf(m0 - mn0), a1 = __expf(m1 - mn1);
        float s0 = 0.f, s1 = 0.f;
#pragma unroll
        for (int nb = 0; nb < 8; nb++) {
            Sf[nb][0] = __expf(Sf[nb][0] - mn0); s0 += Sf[nb][0];
            Sf[nb][1] = __expf(Sf[nb][1] - mn0); s0 += Sf[nb][1];
            Sf[nb][2] = __expf(Sf[nb][2] - mn1); s1 += Sf[nb][2];
            Sf[nb][3] = __expf(Sf[nb][3] - mn1); s1 += Sf[nb][3];
        }
        s0 += __shfl_xor_sync(0xffffffff, s0, 1);
        s0 += __shfl_xor_sync(0xffffffff, s0, 2);
        s1 += __shfl_xor_sync(0xffffffff, s1, 1);
        s1 += __shfl_xor_sync(0xffffffff, s1, 2);
        l0 = l0 * a0 + s0;  l1 = l1 * a1 + s1;
        m0 = mn0;           m1 = mn1;
#pragma unroll
        for (int nb = 0; nb < 16; nb++) {
            Of[nb][0] *= a0; Of[nb][1] *= a0;
            Of[nb][2] *= a1; Of[nb][3] *= a1;
        }

        // O += P V
        const uint32_t vb = kvb + FTILE * 2;
#pragma unroll
        for (int j = 0; j < 4; j++) {
            uint32_t ph[4];
            ph[0] = pack_h2(Sf[2 * j][0],     Sf[2 * j][1]);
            ph[1] = pack_h2(Sf[2 * j][2],     Sf[2 * j][3]);
            ph[2] = pack_h2(Sf[2 * j + 1][0], Sf[2 * j + 1][1]);
            ph[3] = pack_h2(Sf[2 * j + 1][2], Sf[2 * j + 1][3]);
#pragma unroll
            for (int nb2 = 0; nb2 < 8; nb2++) {
                uint32_t addr = vb + ((j * 16 + ldr) * FSTR + nb2 * 16 + ldc) * 2;
                uint32_t vf[4];
                LDMX4T(vf, addr);
                MMA_F16(Of[2 * nb2],     ph, vf[0], vf[1]);
                MMA_F16(Of[2 * nb2 + 1], ph, vf[2], vf[3]);
            }
        }

        __syncthreads();
        if (kt + 2 <= ktmax) load_kv(kt + 2, kt & 1);
    }

    const int b = bh >> 4, h = bh & 15;
    const float inv0 = 1.0f / l0, inv1 = 1.0f / l1;
    const size_t row0 = (size_t)(b * SSQ + q0 + wrow + grp) * DDIM + (h << 7);
    const size_t row1 = row0 + (size_t)8 * DDIM;
#pragma unroll
    for (int nb = 0; nb < 16; nb++) {
        *(uint32_t*)(oh + row0 + nb * 8 + qq) =
            pack_h2(Of[nb][0] * inv0, Of[nb][1] * inv0);
        *(uint32_t*)(oh + row1 + nb * 8 + qq) =
            pack_h2(Of[nb][2] * inv1, Of[nb][3] * inv1);
    }
}

// ---------------------------------------------------------------------------
// Launch
// ---------------------------------------------------------------------------
extern "C" void kernel_launch(void* const* d_in, const int* in_sizes, int n_in,
                              void* d_out, int out_size)
{
    const float* x     = (const float*)d_in[0];
    const float* wqkv  = (const float*)d_in[1];
    const float* wout  = (const float*)d_in[2];
    const float* fcos  = (const float*)d_in[3];
    const float* fsin  = (const float*)d_in[4];
    float* out = (float*)d_out;

    __half *xh, *w1h, *w2h, *ah, *qh, *kh, *vh;
    cudaGetSymbolAddress((void**)&xh,  g_xh);
    cudaGetSymbolAddress((void**)&w1h, g_w1h);
    cudaGetSymbolAddress((void**)&w2h, g_w2h);
    cudaGetSymbolAddress((void**)&ah,  g_ah);
    cudaGetSymbolAddress((void**)&qh,  g_qh);
    cudaGetSymbolAddress((void**)&kh,  g_kh);
    cudaGetSymbolAddress((void**)&vh,  g_vh);

    cudaFuncSetAttribute(mma_gemm_t<0>,
                         cudaFuncAttributeMaxDynamicSharedMemorySize, GEMM_SMEM);
    cudaFuncSetAttribute(mma_gemm_t<1>,
                         cudaFuncAttributeMaxDynamicSharedMemorySize, GEMM_SMEM);
    cudaFuncSetAttribute(flash_mma,
                         cudaFuncAttributeMaxDynamicSharedMemorySize, FLASH_SMEM);

    const int nx  = M1 * DDIM / 4;
    const int nw1 = N1 * DDIM / 4;
    const int nw2 = DDIM * DDIM / 4;

    // operand conversion
    cvt_h<<<(nx  + 255) / 256, 256>>>(x, xh, nx);
    cvt_h<<<(nw1 + 255) / 256, 256>>>(wqkv, w1h, nw1);
    cvt_h<<<(nw2 + 255) / 256, 256>>>(wout, w2h, nw2);

    // 1) QKV projection with fused RoPE + relayout
    mma_gemm_t<1><<<dim3(N1 / 128, M1 / 128), 512, GEMM_SMEM>>>(
        xh, w1h, nullptr, N1, DDIM, fcos, fsin);

    // 2) Flash attention -> g_ah
    flash_mma<<<dim3(SSQ / 128, FB), 256, FLASH_SMEM>>>(qh, kh, vh, ah);

    // 3) Output projection
    mma_gemm_t<0><<<dim3(DDIM / 128, M1 / 128), 512, GEMM_SMEM>>>(
        ah, w2h, out, DDIM, DDIM, nullptr, nullptr);
}

// round 16
// speedup vs baseline: 1.0747x; 1.0747x over previous
#include <cuda_runtime.h>
#include <cuda_fp16.h>
#include <cstdint>

// Problem constants
#define BB 2
#define SSQ 2048
#define DDIM 2048
#define HH 16
#define M1 (BB * SSQ)      // 4096
#define N1 (3 * DDIM)      // 6144
#define FB (BB * HH)       // 32 (b,h) pairs

// ---------------------------------------------------------------------------
// Scratch (__device__ globals). fp16 operands, all 1-digit.
// ---------------------------------------------------------------------------
__device__ __half g_xh [(size_t)M1 * DDIM];
__device__ __half g_w1h[(size_t)N1 * DDIM];
__device__ __half g_w2h[(size_t)DDIM * DDIM];
__device__ __half g_ah [(size_t)M1 * DDIM];           // flash out (GEMM2 A)
// flash operands, layout [bh][s][128]
__device__ __half g_qh[(size_t)FB * SSQ * 128];
__device__ __half g_kh[(size_t)FB * SSQ * 128];
__device__ __half g_vh[(size_t)FB * SSQ * 128];

__device__ __forceinline__ uint32_t smem_u32(const void* p) {
    uint32_t a;
    asm("{ .reg .u64 t; cvta.to.shared.u64 t, %1; cvt.u32.u64 %0, t; }"
        : "=r"(a) : "l"(p));
    return a;
}

#define LDMX4(R, A) \
    asm volatile("ldmatrix.sync.aligned.m8n8.x4.shared.b16 {%0,%1,%2,%3}, [%4];" \
        : "=r"((R)[0]), "=r"((R)[1]), "=r"((R)[2]), "=r"((R)[3]) : "r"(A))
#define LDMX4T(R, A) \
    asm volatile("ldmatrix.sync.aligned.m8n8.x4.trans.shared.b16 {%0,%1,%2,%3}, [%4];" \
        : "=r"((R)[0]), "=r"((R)[1]), "=r"((R)[2]), "=r"((R)[3]) : "r"(A))

#define MMA_F16(ac, a, b0v, b1v) \
    asm volatile("mma.sync.aligned.m16n8k16.row.col.f32.f16.f16.f32 " \
        "{%0,%1,%2,%3},{%4,%5,%6,%7},{%8,%9},{%0,%1,%2,%3};" \
        : "+f"((ac)[0]), "+f"((ac)[1]), "+f"((ac)[2]), "+f"((ac)[3]) \
        : "r"((a)[0]), "r"((a)[1]), "r"((a)[2]), "r"((a)[3]), \
          "r"(b0v), "r"(b1v))

#define CP_ASYNC16(s, g) \
    asm volatile("cp.async.cg.shared.global [%0], [%1], 16;" :: "r"(s), "l"(g))
#define CP_COMMIT() asm volatile("cp.async.commit_group;" ::: "memory")
#define CP_WAIT1()  asm volatile("cp.async.wait_group 1;" ::: "memory")
#define CP_WAIT0()  asm volatile("cp.async.wait_group 0;" ::: "memory")

__device__ __forceinline__ uint32_t pack_h2(float x, float y) {
    __half2 h = __floats2half2_rn(x, y);
    return *reinterpret_cast<uint32_t*>(&h);
}

// ---------------------------------------------------------------------------
// fp32 -> fp16 convert
// ---------------------------------------------------------------------------
__global__ __launch_bounds__(256) void cvt_h(
    const float* __restrict__ src, __half* __restrict__ dst, int n4)
{
    int i = blockIdx.x * blockDim.x + threadIdx.x;
    if (i >= n4) return;
    float4 v = ((const float4*)src)[i];
    ((uint32_t*)dst)[i * 2 + 0] = pack_h2(v.x, v.y);
    ((uint32_t*)dst)[i * 2 + 1] = pack_h2(v.z, v.w);
}

// ---------------------------------------------------------------------------
// mma.sync fp16 GEMM:  C[M,N] = A[M,K] * W[N,K]^T, 1-digit operands,
// fp32 accumulate. CTA 128x128, 256 threads (8 warps, warp tile 64x32),
// k-chunk 64 (4 k16 steps/iter, halved barrier count), double-buffered
// cp.async, 2 CTAs/SM.
//  MODE 0: plain fp32 store;  MODE 1: fused RoPE + relayout (q/k/v)
// ---------------------------------------------------------------------------
#define KC 64
#define AST 72                           // padded row stride (fp16, 144 B)
#define TILE_B 18432                     // one 128x64 tile (bytes)
#define STAGE (2 * TILE_B)               // A, B
#define GEMM_SMEM (2 * STAGE)            // 73728

template <int MODE>
__global__ __launch_bounds__(256, 2) void mma_gemm_t(
    const __half* __restrict__ A, const __half* __restrict__ B,
    float* __restrict__ C, int Ntot, int K,
    const float* __restrict__ fc, const float* __restrict__ fs)
{
    extern __shared__ __half smh[];
    const uint32_t sbase = smem_u32(smh);
    const int t = threadIdx.x;
    const int lane = t & 31, warp = t >> 5;
    const int bm = blockIdx.y << 7;
    const int bn = blockIdx.x << 7;
    const int wm = (warp >> 2) << 6;   // 0 / 64
    const int wn = (warp & 3) << 5;    // 0,32,64,96

    // loader: row t>>1 (0..127), 16B-chunks {4*(t&1)..4*(t&1)+3} of 8/row
    const int lr = t >> 1;
    const int lc0 = (t & 1) << 2;

    const __half* gA = A + (size_t)(bm + lr) * K + lc0 * 8;
    const __half* gB = B + (size_t)(bn + lr) * K + lc0 * 8;
    const uint32_t sA = sbase + (lr * AST + lc0 * 8) * 2;
    const uint32_t sB = sA + TILE_B;

    auto load_stage = [&](int kc, int buf) {
        const uint32_t so = buf * STAGE;
        const int go = kc * KC;
#pragma unroll
        for (int c = 0; c < 4; c++) {
            CP_ASYNC16(sA + so + c * 16, gA + go + c * 8);
            CP_ASYNC16(sB + so + c * 16, gB + go + c * 8);
        }
        CP_COMMIT();
    };

    float acc[4][4][4] = {};
    const int NIT = K / KC;              // 32

    load_stage(0, 0);

    const int ldrow = lane & 15;
    const int ldcol = (lane >> 4) << 3;

    for (int it = 0; it < NIT; it++) {
        if (it + 1 < NIT) { load_stage(it + 1, (it + 1) & 1); CP_WAIT1(); }
        else              { CP_WAIT0(); }
        __syncthreads();

        const uint32_t sb = sbase + (it & 1) * STAGE;
#pragma unroll
        for (int kh = 0; kh < 4; kh++) {
            uint32_t aF[4][4], bF[4][2];
            const int colb = (kh * 16 + ldcol) * 2;
#pragma unroll
            for (int mt = 0; mt < 4; mt++) {
                uint32_t ra = sb + (wm + mt * 16 + ldrow) * (AST * 2) + colb;
                LDMX4(aF[mt], ra);
            }
#pragma unroll
            for (int n2 = 0; n2 < 2; n2++) {
                uint32_t rb = sb + TILE_B +
                              (wn + n2 * 16 + ldrow) * (AST * 2) + colb;
                uint32_t r[4];
                LDMX4(r, rb);
                bF[n2 * 2 + 0][0] = r[0]; bF[n2 * 2 + 0][1] = r[2];
                bF[n2 * 2 + 1][0] = r[1]; bF[n2 * 2 + 1][1] = r[3];
            }
#pragma unroll
            for (int mt = 0; mt < 4; mt++) {
#pragma unroll
                for (int nt = 0; nt < 4; nt++)
                    MMA_F16(acc[mt][nt], aF[mt], bF[nt][0], bF[nt][1]);
            }
        }
        __syncthreads();
    }

    const int grp = lane >> 2, qq = (lane & 3) << 1;

    if (MODE == 0) {
#pragma unroll
        for (int mt = 0; mt < 4; mt++) {
#pragma unroll
            for (int nt = 0; nt < 4; nt++) {
                float* p = C + (size_t)(bm + wm + mt * 16 + grp) * Ntot
                             + bn + wn + nt * 8 + qq;
                *(float2*)p = make_float2(acc[mt][nt][0], acc[mt][nt][1]);
                *(float2*)(p + (size_t)8 * Ntot) =
                    make_float2(acc[mt][nt][2], acc[mt][nt][3]);
            }
        }
    } else {
        // fused RoPE + relayout; CTA-uniform region (q/k/v)
        const int region = bn >> 11;            // 0=q, 1=k, 2=v
        const float scale = 0.08838834764831845f; // 1/sqrt(128)
#pragma unroll
        for (int mt = 0; mt < 4; mt++) {
            const int r0 = bm + wm + mt * 16 + grp;
            const int b  = r0 >> 11;
            const int s0 = r0 & (SSQ - 1);
            const int s1 = s0 + 8;
#pragma unroll
            for (int nt = 0; nt < 4; nt++) {
                const int c  = bn + wn + nt * 8 + qq;
                const int cr = c & (DDIM - 1);
                const int h  = cr >> 7;
                const int ch = cr & 127;
                const int i  = ch >> 1;
                const size_t ob = ((size_t)(b * HH + h) * SSQ);
                const size_t o0 = (ob + s0) * 128 + ch;
                const size_t o1 = (ob + s1) * 128 + ch;
                float x0 = acc[mt][nt][0], y0 = acc[mt][nt][1];
                float x1 = acc[mt][nt][2], y1 = acc[mt][nt][3];
                if (region == 2) {
                    *(uint32_t*)(g_vh + o0) = pack_h2(x0, y0);
                    *(uint32_t*)(g_vh + o1) = pack_h2(x1, y1);
                } else {
                    float c0 = fc[(s0 << 6) + i], sn0 = fs[(s0 << 6) + i];
                    float c1 = fc[(s1 << 6) + i], sn1 = fs[(s1 << 6) + i];
                    float rx0 = x0 * c0 - y0 * sn0, ry0 = x0 * sn0 + y0 * c0;
                    float rx1 = x1 * c1 - y1 * sn1, ry1 = x1 * sn1 + y1 * c1;
                    if (region == 0) {
                        *(uint32_t*)(g_qh + o0) = pack_h2(rx0 * scale, ry0 * scale);
                        *(uint32_t*)(g_qh + o1) = pack_h2(rx1 * scale, ry1 * scale);
                    } else {
                        *(uint32_t*)(g_kh + o0) = pack_h2(rx0, ry0);
                        *(uint32_t*)(g_kh + o1) = pack_h2(rx1, ry1);
                    }
                }
            }
        }
    }
}

// ---------------------------------------------------------------------------
// Flash attention on fp16 mma.sync (fp32 accumulate) — unchanged from R14.
// ---------------------------------------------------------------------------
#define FSTR 136
#define FTILE (64 * FSTR)
#define QTILE (128 * FSTR)
#define FLASH_SMEM ((QTILE + 4 * FTILE) * 2)   // 104448 bytes

__global__ __launch_bounds__(256, 1) void flash_mma(
    const __half* __restrict__ qh_, const __half* __restrict__ kh_,
    const __half* __restrict__ vh_, __half* __restrict__ oh)
{
    extern __shared__ __half fsm[];
    const uint32_t sb = smem_u32(fsm);
    const int t = threadIdx.x;
    const int lane = t & 31, warp = t >> 5;
    const int qt = (int)gridDim.x - 1 - (int)blockIdx.x;
    const int bh = blockIdx.y;
    const int q0 = qt << 7;
    const size_t bhbase = (size_t)bh * SSQ * 128;

    const int ldr = lane & 15;
    const int ldc = (lane >> 4) << 3;
    const int grp = lane >> 2;
    const int qq  = (lane & 3) << 1;

    // stage Q
    {
        int r = t >> 1;
        int e0 = (t & 1) << 6;
        const __half* src = qh_ + bhbase + (size_t)(q0 + r) * 128 + e0;
        uint32_t s0 = sb + (r * FSTR + e0) * 2;
#pragma unroll
        for (int c = 0; c < 8; c++)
            CP_ASYNC16(s0 + c * 16, src + c * 8);
        CP_COMMIT();
    }

    auto load_kv = [&](int kt, int buf) {
        int r = t >> 2;
        int e0 = (t & 3) << 5;
        size_t g0 = bhbase + (size_t)(kt * 64 + r) * 128 + e0;
        const __half* srcs[2] = { kh_ + g0, vh_ + g0 };
        uint32_t s0 = sb + (QTILE + buf * 2 * FTILE + r * FSTR + e0) * 2;
#pragma unroll
        for (int tile = 0; tile < 2; tile++)
#pragma unroll
            for (int c = 0; c < 4; c++)
                CP_ASYNC16(s0 + tile * FTILE * 2 + c * 16, srcs[tile] + c * 8);
        CP_COMMIT();
    };

    CP_WAIT0();
    __syncthreads();
    uint32_t qf[8][4];
    const int wrow = warp << 4;
#pragma unroll
    for (int d = 0; d < 8; d++) {
        uint32_t a = sb + ((wrow + ldr) * FSTR + d * 16 + ldc) * 2;
        LDMX4(qf[d], a);
    }

    const int ktmax = 2 * qt + 1;
    load_kv(0, 0);
    load_kv(1, 1);

    float Of[16][4] = {};
    float m0 = -1e30f, m1 = -1e30f, l0 = 0.f, l1 = 0.f;

    for (int kt = 0; kt <= ktmax; kt++) {
        if (kt == ktmax) { CP_WAIT0(); } else { CP_WAIT1(); }
        __syncthreads();

        const uint32_t kvb = sb + (QTILE + (kt & 1) * 2 * FTILE) * 2;

        float Sf[8][4] = {};
#pragma unroll
        for (int d = 0; d < 8; d++) {
#pragma unroll
            for (int n4 = 0; n4 < 4; n4++) {
                uint32_t addr = kvb + ((n4 * 16 + ldr) * FSTR + d * 16 + ldc) * 2;
                uint32_t kb[4];
                LDMX4(kb, addr);
                MMA_F16(Sf[2 * n4],     qf[d], kb[0], kb[2]);
                MMA_F16(Sf[2 * n4 + 1], qf[d], kb[1], kb[3]);
            }
        }

        const int r0 = q0 + wrow + grp;
        if (kt >= 2 * qt) {
#pragma unroll
            for (int nb = 0; nb < 8; nb++) {
#pragma unroll
                for (int j = 0; j < 2; j++) {
                    int key = kt * 64 + nb * 8 + qq + j;
                    if (key > r0)     Sf[nb][j]     = -1e30f;
                    if (key > r0 + 8) Sf[nb][2 + j] = -1e30f;
                }
            }
        }

        float mx0 = -1e30f, mx1 = -1e30f;
#pragma unroll
        for (int nb = 0; nb < 8; nb++) {
            mx0 = fmaxf(mx0, fmaxf(Sf[nb][0], Sf[nb][1]));
            mx1 = fmaxf(mx1, fmaxf(Sf[nb][2], Sf[nb][3]));
        }
        mx0 = fmaxf(mx0, __shfl_xor_sync(0xffffffff, mx0, 1));
        mx0 = fmaxf(mx0, __shfl_xor_sync(0xffffffff, mx0, 2));
        mx1 = fmaxf(mx1, __shfl_xor_sync(0xffffffff, mx1, 1));
        mx1 = fmaxf(mx1, __shfl_xor_sync(0xffffffff, mx1, 2));
        float mn0 = fmaxf(m0, mx0), mn1 = fmaxf(m1, mx1);
        float a0 = __expf(m0 - mn0), a1 = __expf(m1 - mn1);
        float s0 = 0.f, s1 = 0.f;
#pragma unroll
        for (int nb = 0; nb < 8; nb++) {
            Sf[nb][0] = __expf(Sf[nb][0] - mn0); s0 += Sf[nb][0];
            Sf[nb][1] = __expf(Sf[nb][1] - mn0); s0 += Sf[nb][1];
            Sf[nb][2] = __expf(Sf[nb][2] - mn1); s1 += Sf[nb][2];
            Sf[nb][3] = __expf(Sf[nb][3] - mn1); s1 += Sf[nb][3];
        }
        s0 += __shfl_xor_sync(0xffffffff, s0, 1);
        s0 += __shfl_xor_sync(0xffffffff, s0, 2);
        s1 += __shfl_xor_sync(0xffffffff, s1, 1);
        s1 += __shfl_xor_sync(0xffffffff, s1, 2);
        l0 = l0 * a0 + s0;  l1 = l1 * a1 + s1;
        m0 = mn0;           m1 = mn1;
#pragma unroll
        for (int nb = 0; nb < 16; nb++) {
            Of[nb][0] *= a0; Of[nb][1] *= a0;
            Of[nb][2] *= a1; Of[nb][3] *= a1;
        }

        // O += P V
        const uint32_t vb = kvb + FTILE * 2;
#pragma unroll
        for (int j = 0; j < 4; j++) {
            uint32_t ph[4];
            ph[0] = pack_h2(Sf[2 * j][0],     Sf[2 * j][1]);
            ph[1] = pack_h2(Sf[2 * j][2],     Sf[2 * j][3]);
            ph[2] = pack_h2(Sf[2 * j + 1][0], Sf[2 * j + 1][1]);
            ph[3] = pack_h2(Sf[2 * j + 1][2], Sf[2 * j + 1][3]);
#pragma unroll
            for (int nb2 = 0; nb2 < 8; nb2++) {
                uint32_t addr = vb + ((j * 16 + ldr) * FSTR + nb2 * 16 + ldc) * 2;
                uint32_t vf[4];
                LDMX4T(vf, addr);
                MMA_F16(Of[2 * nb2],     ph, vf[0], vf[1]);
                MMA_F16(Of[2 * nb2 + 1], ph, vf[2], vf[3]);
            }
        }

        __syncthreads();
        if (kt + 2 <= ktmax) load_kv(kt + 2, kt & 1);
    }

    const int b = bh >> 4, h = bh & 15;
    const float inv0 = 1.0f / l0, inv1 = 1.0f / l1;
    const size_t row0 = (size_t)(b * SSQ + q0 + wrow + grp) * DDIM + (h << 7);
    const size_t row1 = row0 + (size_t)8 * DDIM;
#pragma unroll
    for (int nb = 0; nb < 16; nb++) {
        *(uint32_t*)(oh + row0 + nb * 8 + qq) =
            pack_h2(Of[nb][0] * inv0, Of[nb][1] * inv0);
        *(uint32_t*)(oh + row1 + nb * 8 + qq) =
            pack_h2(Of[nb][2] * inv1, Of[nb][3] * inv1);
    }
}

// ---------------------------------------------------------------------------
// Launch
// ---------------------------------------------------------------------------
extern "C" void kernel_launch(void* const* d_in, const int* in_sizes, int n_in,
                              void* d_out, int out_size)
{
    const float* x     = (const float*)d_in[0];
    const float* wqkv  = (const float*)d_in[1];
    const float* wout  = (const float*)d_in[2];
    const float* fcos  = (const float*)d_in[3];
    const float* fsin  = (const float*)d_in[4];
    float* out = (float*)d_out;

    __half *xh, *w1h, *w2h, *ah, *qh, *kh, *vh;
    cudaGetSymbolAddress((void**)&xh,  g_xh);
    cudaGetSymbolAddress((void**)&w1h, g_w1h);
    cudaGetSymbolAddress((void**)&w2h, g_w2h);
    cudaGetSymbolAddress((void**)&ah,  g_ah);
    cudaGetSymbolAddress((void**)&qh,  g_qh);
    cudaGetSymbolAddress((void**)&kh,  g_kh);
    cudaGetSymbolAddress((void**)&vh,  g_vh);

    cudaFuncSetAttribute(mma_gemm_t<0>,
                         cudaFuncAttributeMaxDynamicSharedMemorySize, GEMM_SMEM);
    cudaFuncSetAttribute(mma_gemm_t<1>,
                         cudaFuncAttributeMaxDynamicSharedMemorySize, GEMM_SMEM);
    cudaFuncSetAttribute(flash_mma,
                         cudaFuncAttributeMaxDynamicSharedMemorySize, FLASH_SMEM);

    const int nx  = M1 * DDIM / 4;
    const int nw1 = N1 * DDIM / 4;
    const int nw2 = DDIM * DDIM / 4;

    // operand conversion
    cvt_h<<<(nx  + 255) / 256, 256>>>(x, xh, nx);
    cvt_h<<<(nw1 + 255) / 256, 256>>>(wqkv, w1h, nw1);
    cvt_h<<<(nw2 + 255) / 256, 256>>>(wout, w2h, nw2);

    // 1) QKV projection with fused RoPE + relayout
    mma_gemm_t<1><<<dim3(N1 / 128, M1 / 128), 256, GEMM_SMEM>>>(
        xh, w1h, nullptr, N1, DDIM, fcos, fsin);

    // 2) Flash attention -> g_ah
    flash_mma<<<dim3(SSQ / 128, FB), 256, FLASH_SMEM>>>(qh, kh, vh, ah);

    // 3) Output projection
    mma_gemm_t<0><<<dim3(DDIM / 128, M1 / 128), 256, GEMM_SMEM>>>(
        ah, w2h, out, DDIM, DDIM, nullptr, nullptr);
}

// round 17
// speedup vs baseline: 1.1593x; 1.0787x over previous
#include <cuda_runtime.h>
#include <cuda_fp16.h>
#include <cstdint>

// Problem constants
#define BB 2
#define SSQ 2048
#define DDIM 2048
#define HH 16
#define M1 (BB * SSQ)      // 4096
#define N1 (3 * DDIM)      // 6144
#define FB (BB * HH)       // 32 (b,h) pairs

// ---------------------------------------------------------------------------
// Scratch (__device__ globals). fp16 operands, all 1-digit.
// ---------------------------------------------------------------------------
__device__ __half g_xh [(size_t)M1 * DDIM];
__device__ __half g_w1h[(size_t)N1 * DDIM];
__device__ __half g_w2h[(size_t)DDIM * DDIM];
__device__ __half g_ah [(size_t)M1 * DDIM];           // flash out (GEMM2 A)
// flash operands, layout [bh][s][128]
__device__ __half g_qh[(size_t)FB * SSQ * 128];
__device__ __half g_kh[(size_t)FB * SSQ * 128];
__device__ __half g_vh[(size_t)FB * SSQ * 128];

__device__ __forceinline__ uint32_t smem_u32(const void* p) {
    uint32_t a;
    asm("{ .reg .u64 t; cvta.to.shared.u64 t, %1; cvt.u32.u64 %0, t; }"
        : "=r"(a) : "l"(p));
    return a;
}

#define LDMX4(R, A) \
    asm volatile("ldmatrix.sync.aligned.m8n8.x4.shared.b16 {%0,%1,%2,%3}, [%4];" \
        : "=r"((R)[0]), "=r"((R)[1]), "=r"((R)[2]), "=r"((R)[3]) : "r"(A))
#define LDMX4T(R, A) \
    asm volatile("ldmatrix.sync.aligned.m8n8.x4.trans.shared.b16 {%0,%1,%2,%3}, [%4];" \
        : "=r"((R)[0]), "=r"((R)[1]), "=r"((R)[2]), "=r"((R)[3]) : "r"(A))

#define MMA_F16(ac, a, b0v, b1v) \
    asm volatile("mma.sync.aligned.m16n8k16.row.col.f32.f16.f16.f32 " \
        "{%0,%1,%2,%3},{%4,%5,%6,%7},{%8,%9},{%0,%1,%2,%3};" \
        : "+f"((ac)[0]), "+f"((ac)[1]), "+f"((ac)[2]), "+f"((ac)[3]) \
        : "r"((a)[0]), "r"((a)[1]), "r"((a)[2]), "r"((a)[3]), \
          "r"(b0v), "r"(b1v))

#define CP_ASYNC16(s, g) \
    asm volatile("cp.async.cg.shared.global [%0], [%1], 16;" :: "r"(s), "l"(g))
#define CP_COMMIT() asm volatile("cp.async.commit_group;" ::: "memory")
#define CP_WAIT1()  asm volatile("cp.async.wait_group 1;" ::: "memory")
#define CP_WAIT0()  asm volatile("cp.async.wait_group 0;" ::: "memory")

__device__ __forceinline__ uint32_t pack_h2(float x, float y) {
    __half2 h = __floats2half2_rn(x, y);
    return *reinterpret_cast<uint32_t*>(&h);
}

// ---------------------------------------------------------------------------
// fp32 -> fp16 convert
// ---------------------------------------------------------------------------
__global__ __launch_bounds__(256) void cvt_h(
    const float* __restrict__ src, __half* __restrict__ dst, int n4)
{
    int i = blockIdx.x * blockDim.x + threadIdx.x;
    if (i >= n4) return;
    float4 v = ((const float4*)src)[i];
    ((uint32_t*)dst)[i * 2 + 0] = pack_h2(v.x, v.y);
    ((uint32_t*)dst)[i * 2 + 1] = pack_h2(v.z, v.w);
}

// ---------------------------------------------------------------------------
// mma.sync fp16 GEMM:  C[M,N] = A[M,K] * W[N,K]^T, 1-digit operands,
// fp32 accumulate. CTA 128x128, 256 threads (8 warps, warp tile 64x32),
// k-chunk 32, double-buffered cp.async, 2 CTAs/SM.
// All 12 LDSMs of an iteration are hoisted ahead of all 32 MMAs
// (fragment arrays span both kh steps) to break the LDSM->MMA chain.
//  MODE 0: plain fp32 store;  MODE 1: fused RoPE + relayout (q/k/v)
// ---------------------------------------------------------------------------
#define KC 32
#define AST 40                           // padded row stride (fp16, 80 B)
#define TILE_B 10240                     // one 128x32 tile (bytes)
#define STAGE (2 * TILE_B)               // A, B
#define GEMM_SMEM (2 * STAGE)            // 40960

template <int MODE>
__global__ __launch_bounds__(256, 2) void mma_gemm_t(
    const __half* __restrict__ A, const __half* __restrict__ B,
    float* __restrict__ C, int Ntot, int K,
    const float* __restrict__ fc, const float* __restrict__ fs)
{
    extern __shared__ __half smh[];
    const uint32_t sbase = smem_u32(smh);
    const int t = threadIdx.x;
    const int lane = t & 31, warp = t >> 5;
    const int bm = blockIdx.y << 7;
    const int bn = blockIdx.x << 7;
    const int wm = (warp >> 2) << 6;   // 0 / 64
    const int wn = (warp & 3) << 5;    // 0,32,64,96

    const int lr = t >> 1;
    const int lc0 = (t & 1) << 1;

    const __half* gsrc[2] = {
        A + (size_t)(bm + lr) * K,
        B + (size_t)(bn + lr) * K };

    auto load_stage = [&](int kc, int buf) {
        uint32_t sb = sbase + buf * STAGE;
#pragma unroll
        for (int tile = 0; tile < 2; tile++) {
#pragma unroll
            for (int i = 0; i < 2; i++) {
                int c = lc0 + i;
                uint32_t sa = sb + tile * TILE_B + (lr * AST + c * 8) * 2;
                const void* ga = gsrc[tile] + kc * KC + c * 8;
                CP_ASYNC16(sa, ga);
            }
        }
        CP_COMMIT();
    };

    float acc[4][4][4] = {};
    const int NIT = K / KC;

    load_stage(0, 0);

    const int ldrow = lane & 15;
    const int ldcol = (lane >> 4) << 3;

    for (int it = 0; it < NIT; it++) {
        if (it + 1 < NIT) { load_stage(it + 1, (it + 1) & 1); CP_WAIT1(); }
        else              { CP_WAIT0(); }
        __syncthreads();

        const uint32_t sb = sbase + (it & 1) * STAGE;
        uint32_t aF[2][4][4], bF[2][4][2];
        // hoist ALL fragment loads for both kh steps
#pragma unroll
        for (int kh = 0; kh < 2; kh++) {
            const int colb = (kh * 16 + ldcol) * 2;
#pragma unroll
            for (int mt = 0; mt < 4; mt++) {
                uint32_t ra = sb + (wm + mt * 16 + ldrow) * (AST * 2) + colb;
                LDMX4(aF[kh][mt], ra);
            }
#pragma unroll
            for (int n2 = 0; n2 < 2; n2++) {
                uint32_t rb = sb + TILE_B +
                              (wn + n2 * 16 + ldrow) * (AST * 2) + colb;
                uint32_t r[4];
                LDMX4(r, rb);
                bF[kh][n2 * 2 + 0][0] = r[0]; bF[kh][n2 * 2 + 0][1] = r[2];
                bF[kh][n2 * 2 + 1][0] = r[1]; bF[kh][n2 * 2 + 1][1] = r[3];
            }
        }
        // then ALL MMAs
#pragma unroll
        for (int kh = 0; kh < 2; kh++) {
#pragma unroll
            for (int mt = 0; mt < 4; mt++) {
#pragma unroll
                for (int nt = 0; nt < 4; nt++)
                    MMA_F16(acc[mt][nt], aF[kh][mt],
                            bF[kh][nt][0], bF[kh][nt][1]);
            }
        }
        __syncthreads();
    }

    const int grp = lane >> 2, qq = (lane & 3) << 1;

    if (MODE == 0) {
#pragma unroll
        for (int mt = 0; mt < 4; mt++) {
#pragma unroll
            for (int nt = 0; nt < 4; nt++) {
                float* p = C + (size_t)(bm + wm + mt * 16 + grp) * Ntot
                             + bn + wn + nt * 8 + qq;
                *(float2*)p = make_float2(acc[mt][nt][0], acc[mt][nt][1]);
                *(float2*)(p + (size_t)8 * Ntot) =
                    make_float2(acc[mt][nt][2], acc[mt][nt][3]);
            }
        }
    } else {
        // fused RoPE + relayout; CTA-uniform region (q/k/v)
        const int region = bn >> 11;            // 0=q, 1=k, 2=v
        const float scale = 0.08838834764831845f; // 1/sqrt(128)
#pragma unroll
        for (int mt = 0; mt < 4; mt++) {
            const int r0 = bm + wm + mt * 16 + grp;
            const int b  = r0 >> 11;
            const int s0 = r0 & (SSQ - 1);
            const int s1 = s0 + 8;
#pragma unroll
            for (int nt = 0; nt < 4; nt++) {
                const int c  = bn + wn + nt * 8 + qq;
                const int cr = c & (DDIM - 1);
                const int h  = cr >> 7;
                const int ch = cr & 127;
                const int i  = ch >> 1;
                const size_t ob = ((size_t)(b * HH + h) * SSQ);
                const size_t o0 = (ob + s0) * 128 + ch;
                const size_t o1 = (ob + s1) * 128 + ch;
                float x0 = acc[mt][nt][0], y0 = acc[mt][nt][1];
                float x1 = acc[mt][nt][2], y1 = acc[mt][nt][3];
                if (region == 2) {
                    *(uint32_t*)(g_vh + o0) = pack_h2(x0, y0);
                    *(uint32_t*)(g_vh + o1) = pack_h2(x1, y1);
                } else {
                    float c0 = fc[(s0 << 6) + i], sn0 = fs[(s0 << 6) + i];
                    float c1 = fc[(s1 << 6) + i], sn1 = fs[(s1 << 6) + i];
                    float rx0 = x0 * c0 - y0 * sn0, ry0 = x0 * sn0 + y0 * c0;
                    float rx1 = x1 * c1 - y1 * sn1, ry1 = x1 * sn1 + y1 * c1;
                    if (region == 0) {
                        *(uint32_t*)(g_qh + o0) = pack_h2(rx0 * scale, ry0 * scale);
                        *(uint32_t*)(g_qh + o1) = pack_h2(rx1 * scale, ry1 * scale);
                    } else {
                        *(uint32_t*)(g_kh + o0) = pack_h2(rx0, ry0);
                        *(uint32_t*)(g_kh + o1) = pack_h2(rx1, ry1);
                    }
                }
            }
        }
    }
}

// ---------------------------------------------------------------------------
// Flash attention on fp16 mma.sync (fp32 accumulate) — unchanged from R14.
// ---------------------------------------------------------------------------
#define FSTR 136
#define FTILE (64 * FSTR)
#define QTILE (128 * FSTR)
#define FLASH_SMEM ((QTILE + 4 * FTILE) * 2)   // 104448 bytes

__global__ __launch_bounds__(256, 1) void flash_mma(
    const __half* __restrict__ qh_, const __half* __restrict__ kh_,
    const __half* __restrict__ vh_, __half* __restrict__ oh)
{
    extern __shared__ __half fsm[];
    const uint32_t sb = smem_u32(fsm);
    const int t = threadIdx.x;
    const int lane = t & 31, warp = t >> 5;
    const int qt = (int)gridDim.x - 1 - (int)blockIdx.x;
    const int bh = blockIdx.y;
    const int q0 = qt << 7;
    const size_t bhbase = (size_t)bh * SSQ * 128;

    const int ldr = lane & 15;
    const int ldc = (lane >> 4) << 3;
    const int grp = lane >> 2;
    const int qq  = (lane & 3) << 1;

    // stage Q
    {
        int r = t >> 1;
        int e0 = (t & 1) << 6;
        const __half* src = qh_ + bhbase + (size_t)(q0 + r) * 128 + e0;
        uint32_t s0 = sb + (r * FSTR + e0) * 2;
#pragma unroll
        for (int c = 0; c < 8; c++)
            CP_ASYNC16(s0 + c * 16, src + c * 8);
        CP_COMMIT();
    }

    auto load_kv = [&](int kt, int buf) {
        int r = t >> 2;
        int e0 = (t & 3) << 5;
        size_t g0 = bhbase + (size_t)(kt * 64 + r) * 128 + e0;
        const __half* srcs[2] = { kh_ + g0, vh_ + g0 };
        uint32_t s0 = sb + (QTILE + buf * 2 * FTILE + r * FSTR + e0) * 2;
#pragma unroll
        for (int tile = 0; tile < 2; tile++)
#pragma unroll
            for (int c = 0; c < 4; c++)
                CP_ASYNC16(s0 + tile * FTILE * 2 + c * 16, srcs[tile] + c * 8);
        CP_COMMIT();
    };

    CP_WAIT0();
    __syncthreads();
    uint32_t qf[8][4];
    const int wrow = warp << 4;
#pragma unroll
    for (int d = 0; d < 8; d++) {
        uint32_t a = sb + ((wrow + ldr) * FSTR + d * 16 + ldc) * 2;
        LDMX4(qf[d], a);
    }

    const int ktmax = 2 * qt + 1;
    load_kv(0, 0);
    load_kv(1, 1);

    float Of[16][4] = {};
    float m0 = -1e30f, m1 = -1e30f, l0 = 0.f, l1 = 0.f;

    for (int kt = 0; kt <= ktmax; kt++) {
        if (kt == ktmax) { CP_WAIT0(); } else { CP_WAIT1(); }
        __syncthreads();

        const uint32_t kvb = sb + (QTILE + (kt & 1) * 2 * FTILE) * 2;

        float Sf[8][4] = {};
#pragma unroll
        for (int d = 0; d < 8; d++) {
#pragma unroll
            for (int n4 = 0; n4 < 4; n4++) {
                uint32_t addr = kvb + ((n4 * 16 + ldr) * FSTR + d * 16 + ldc) * 2;
                uint32_t kb[4];
                LDMX4(kb, addr);
                MMA_F16(Sf[2 * n4],     qf[d], kb[0], kb[2]);
                MMA_F16(Sf[2 * n4 + 1], qf[d], kb[1], kb[3]);
            }
        }

        const int r0 = q0 + wrow + grp;
        if (kt >= 2 * qt) {
#pragma unroll
            for (int nb = 0; nb < 8; nb++) {
#pragma unroll
                for (int j = 0; j < 2; j++) {
                    int key = kt * 64 + nb * 8 + qq + j;
                    if (key > r0)     Sf[nb][j]     = -1e30f;
                    if (key > r0 + 8) Sf[nb][2 + j] = -1e30f;
                }
            }
        }

        float mx0 = -1e30f, mx1 = -1e30f;
#pragma unroll
        for (int nb = 0; nb < 8; nb++) {
            mx0 = fmaxf(mx0, fmaxf(Sf[nb][0], Sf[nb][1]));
            mx1 = fmaxf(mx1, fmaxf(Sf[nb][2], Sf[nb][3]));
        }
        mx0 = fmaxf(mx0, __shfl_xor_sync(0xffffffff, mx0, 1));
        mx0 = fmaxf(mx0, __shfl_xor_sync(0xffffffff, mx0, 2));
        mx1 = fmaxf(mx1, __shfl_xor_sync(0xffffffff, mx1, 1));
        mx1 = fmaxf(mx1, __shfl_xor_sync(0xffffffff, mx1, 2));
        float mn0 = fmaxf(m0, mx0), mn1 = fmaxf(m1, mx1);
        float a0 = __expf(m0 - mn0), a1 = __expf(m1 - mn1);
        float s0 = 0.f, s1 = 0.f;
#pragma unroll
        for (int nb = 0; nb < 8; nb++) {
            Sf[nb][0] = __expf(Sf[nb][0] - mn0); s0 += Sf[nb][0];
            Sf[nb][1] = __expf(Sf[nb][1] - mn0); s0 += Sf[nb][1];
            Sf[nb][2] = __expf(Sf[nb][2] - mn1); s1 += Sf[nb][2];
            Sf[nb][3] = __expf(Sf[nb][3] - mn1); s1 += Sf[nb][3];
        }
        s0 += __shfl_xor_sync(0xffffffff, s0, 1);
        s0 += __shfl_xor_sync(0xffffffff, s0, 2);
        s1 += __shfl_xor_sync(0xffffffff, s1, 1);
        s1 += __shfl_xor_sync(0xffffffff, s1, 2);
        l0 = l0 * a0 + s0;  l1 = l1 * a1 + s1;
        m0 = mn0;           m1 = mn1;
#pragma unroll
        for (int nb = 0; nb < 16; nb++) {
            Of[nb][0] *= a0; Of[nb][1] *= a0;
            Of[nb][2] *= a1; Of[nb][3] *= a1;
        }

        // O += P V
        const uint32_t vb = kvb + FTILE * 2;
#pragma unroll
        for (int j = 0; j < 4; j++) {
            uint32_t ph[4];
            ph[0] = pack_h2(Sf[2 * j][0],     Sf[2 * j][1]);
            ph[1] = pack_h2(Sf[2 * j][2],     Sf[2 * j][3]);
            ph[2] = pack_h2(Sf[2 * j + 1][0], Sf[2 * j + 1][1]);
            ph[3] = pack_h2(Sf[2 * j + 1][2], Sf[2 * j + 1][3]);
#pragma unroll
            for (int nb2 = 0; nb2 < 8; nb2++) {
                uint32_t addr = vb + ((j * 16 + ldr) * FSTR + nb2 * 16 + ldc) * 2;
                uint32_t vf[4];
                LDMX4T(vf, addr);
                MMA_F16(Of[2 * nb2],     ph, vf[0], vf[1]);
                MMA_F16(Of[2 * nb2 + 1], ph, vf[2], vf[3]);
            }
        }

        __syncthreads();
        if (kt + 2 <= ktmax) load_kv(kt + 2, kt & 1);
    }

    const int b = bh >> 4, h = bh & 15;
    const float inv0 = 1.0f / l0, inv1 = 1.0f / l1;
    const size_t row0 = (size_t)(b * SSQ + q0 + wrow + grp) * DDIM + (h << 7);
    const size_t row1 = row0 + (size_t)8 * DDIM;
#pragma unroll
    for (int nb = 0; nb < 16; nb++) {
        *(uint32_t*)(oh + row0 + nb * 8 + qq) =
            pack_h2(Of[nb][0] * inv0, Of[nb][1] * inv0);
        *(uint32_t*)(oh + row1 + nb * 8 + qq) =
            pack_h2(Of[nb][2] * inv1, Of[nb][3] * inv1);
    }
}

// ---------------------------------------------------------------------------
// Launch
// ---------------------------------------------------------------------------
extern "C" void kernel_launch(void* const* d_in, const int* in_sizes, int n_in,
                              void* d_out, int out_size)
{
    const float* x     = (const float*)d_in[0];
    const float* wqkv  = (const float*)d_in[1];
    const float* wout  = (const float*)d_in[2];
    const float* fcos  = (const float*)d_in[3];
    const float* fsin  = (const float*)d_in[4];
    float* out = (float*)d_out;

    __half *xh, *w1h, *w2h, *ah, *qh, *kh, *vh;
    cudaGetSymbolAddress((void**)&xh,  g_xh);
    cudaGetSymbolAddress((void**)&w1h, g_w1h);
    cudaGetSymbolAddress((void**)&w2h, g_w2h);
    cudaGetSymbolAddress((void**)&ah,  g_ah);
    cudaGetSymbolAddress((void**)&qh,  g_qh);
    cudaGetSymbolAddress((void**)&kh,  g_kh);
    cudaGetSymbolAddress((void**)&vh,  g_vh);

    cudaFuncSetAttribute(mma_gemm_t<0>,
                         cudaFuncAttributeMaxDynamicSharedMemorySize, GEMM_SMEM);
    cudaFuncSetAttribute(mma_gemm_t<1>,
                         cudaFuncAttributeMaxDynamicSharedMemorySize, GEMM_SMEM);
    cudaFuncSetAttribute(flash_mma,
                         cudaFuncAttributeMaxDynamicSharedMemorySize, FLASH_SMEM);

    const int nx  = M1 * DDIM / 4;
    const int nw1 = N1 * DDIM / 4;
    const int nw2 = DDIM * DDIM / 4;

    // operand conversion
    cvt_h<<<(nx  + 255) / 256, 256>>>(x, xh, nx);
    cvt_h<<<(nw1 + 255) / 256, 256>>>(wqkv, w1h, nw1);
    cvt_h<<<(nw2 + 255) / 256, 256>>>(wout, w2h, nw2);

    // 1) QKV projection with fused RoPE + relayout
    mma_gemm_t<1><<<dim3(N1 / 128, M1 / 128), 256, GEMM_SMEM>>>(
        xh, w1h, nullptr, N1, DDIM, fcos, fsin);

    // 2) Flash attention -> g_ah
    flash_mma<<<dim3(SSQ / 128, FB), 256, FLASH_SMEM>>>(qh, kh, vh, ah);

    // 3) Output projection
    mma_gemm_t<0><<<dim3(DDIM / 128, M1 / 128), 256, GEMM_SMEM>>>(
        ah, w2h, out, DDIM, DDIM, nullptr, nullptr);
}